// round 11
// baseline (speedup 1.0000x reference)
#include <cuda_runtime.h>
#include <cstdint>

#define NTAG      48
#define START_TAG 46
#define STOP_TAG  47
#define BB        128
#define TT        256
#define RS        50                 // padded row stride: matvec LDS covers all 32 banks
#define TILE_ELEMS (NTAG * RS)       // 2400
#define NBUF      8                  // raw-tile ring (cp.async)
#define NTHREADS  384                // 12 warps; j = tid>>3, s = tid&7

// dynamic smem: tiles | P[2][48] | s_inv[2] | s_q0[256] | s_tgt[256] | s_red[384] | isLast
#define SMEM_FLOATS (NBUF * TILE_ELEMS + 96 + 2 + TT + TT + NTHREADS + 4)
#define SMEM_BYTES  (SMEM_FLOATS * 4)

__device__ float        g_partials[BB];
__device__ unsigned int g_count = 0;

__device__ __forceinline__ float rcp_approx(float x) {
    float y;
    asm("rcp.approx.f32 %0, %1;" : "=f"(y) : "f"(x));
    return y;
}
__device__ __forceinline__ void cp_async8(uint32_t dst, const void* src) {
    unsigned long long gsrc;
    asm volatile("cvta.to.global.u64 %0, %1;\n" : "=l"(gsrc) : "l"(src));
    asm volatile("cp.async.ca.shared.global [%0], [%1], 8;\n" :: "r"(dst), "l"(gsrc));
}
__device__ __forceinline__ void cp_commit() {
    asm volatile("cp.async.commit_group;\n" ::: "memory");
}
__device__ __forceinline__ void cp_wait2() {
    asm volatile("cp.async.wait_group 2;\n" ::: "memory");
}

// 48x48 f32 tile (192B rows) -> padded SMEM (200B stride). 3 x 8B per thread.
__device__ __forceinline__ void load_tile(uint32_t sbase, const float* g, int tid) {
    const int r0   = tid / 24;
    const int off8 = (tid % 24) * 8;
    #pragma unroll
    for (int it = 0; it < 3; ++it) {
        const int row = r0 + 16 * it;
        cp_async8(sbase + (uint32_t)(row * (RS * 4) + off8),
                  (const char*)g + row * (NTAG * 4) + off8);
    }
}

__global__ void __launch_bounds__(NTHREADS, 1) viterbi_fwd(
    const float* __restrict__ feats,
    const void* __restrict__ targets_raw,
    const void* __restrict__ lengths_raw,
    float* __restrict__ out)
{
    extern __shared__ __align__(16) float smem[];
    float* tiles    = smem;                       // NBUF * TILE_ELEMS (raw features)
    float* P        = smem + NBUF * TILE_ELEMS;   // 2 * 48
    float* s_inv    = P + 96;                     // 2
    float* s_q0     = s_inv + 2;                  // 256
    int*   s_tgt    = (int*)(s_q0 + TT);          // 256
    float* s_red    = (float*)(s_tgt + TT);       // 384
    int*   s_isLast = (int*)(s_red + NTHREADS);

    const int b   = blockIdx.x;
    const int tid = threadIdx.x;

    // dtype probe: genuine int64 length[0] lies in [1,256]; int32-misread >= 2^32.
    const long long probe = ((const long long*)lengths_raw)[0];
    const bool is64 = (probe >= 1 && probe <= TT);

    int len = is64 ? (int)((const long long*)lengths_raw)[b]
                   : ((const int*)lengths_raw)[b];
    if (len < 1)  len = 1;
    if (len > TT) len = TT;
    const float* fb = feats + (size_t)b * TT * (NTAG * NTAG);

    const uint32_t tbase0 = (uint32_t)__cvta_generic_to_shared(tiles);

    for (int c = tid; c < TT; c += NTHREADS) {
        int v = is64 ? (int)((const long long*)targets_raw)[(size_t)b * TT + c]
                     : ((const int*)targets_raw)[(size_t)b * TT + c];
        if (v < 0) v = 0;
        if (v >= NTAG * NTAG) v = NTAG * NTAG - 1;
        s_tgt[c] = v;
    }

    // ---- prologue: commit tiles 0..4 (one group each; empty if past end) ----
    #pragma unroll
    for (int p = 0; p < 5; ++p) {
        if (p < len)
            load_tile(tbase0 + (uint32_t)(p * TILE_ELEMS * 4),
                      fb + (size_t)p * (NTAG * NTAG), tid);
        cp_commit();
    }
    cp_wait2();                 // tiles 0,1,2 resident
    __syncthreads();            // cross-warp visibility of tiles 0..2 + s_tgt

    // init: P_0[j] = exp(raw tile0[START,:]); gold t=0; scale for t=1.
    if (tid < NTAG) {
        const float p = __expf(tiles[START_TAG * RS + tid]);
        P[tid] = p;
        if (tid == 0) {
            s_inv[1] = rcp_approx(p);
            s_q0[0]  = p;
        }
    }
    float goldAcc = 0.0f;
    if (tid == 0) {
        const int tg = s_tgt[0];
        goldAcc = tiles[(tg / NTAG) * RS + (tg % NTAG)];
    }
    __syncthreads();            // publish P_0 / s_inv before prefetch below

    const int j = tid >> 3;                 // destination tag
    const int s = tid & 7;                  // source slice (6 rows)
    const int co = (s * 6) * RS + j;        // matvec base offset into a tile

    // ---- software-pipeline preload ----
    float w[2][6];              // w[t&1] = exp(tile t) elements for this thread
    float Pr[6];                // P_{t-1}[s*6 .. s*6+5] for the upcoming iter
    float inv;

    if (len > 1) {
        const float* E1 = tiles + 1 * TILE_ELEMS + co;
        #pragma unroll
        for (int k = 0; k < 6; ++k) w[1][k] = __expf(E1[k * RS]);
    }
    if (len > 2) {
        const float* E2 = tiles + 2 * TILE_ELEMS + co;
        #pragma unroll
        for (int k = 0; k < 6; ++k) w[0][k] = __expf(E2[k * RS]);
    }
    #pragma unroll
    for (int k = 0; k < 6; ++k) Pr[k] = P[s * 6 + k];   // P_0 lives in slot 0
    inv = s_inv[1];

    #pragma unroll 2
    for (int t = 1; t < len; ++t) {
        // fast chain: everything it needs is already in registers
        float acc0 = w[t & 1][0] * Pr[0] + w[t & 1][1] * Pr[1] + w[t & 1][2] * Pr[2];
        float acc1 = w[t & 1][3] * Pr[3] + w[t & 1][4] * Pr[4] + w[t & 1][5] * Pr[5];
        float acc  = (acc0 + acc1) * inv;
        acc += __shfl_xor_sync(0xffffffffu, acc, 1);
        acc += __shfl_xor_sync(0xffffffffu, acc, 2);
        acc += __shfl_xor_sync(0xffffffffu, acc, 4);

        if (s == 0) P[(t & 1) * NTAG + j] = acc;
        if (tid == 0) {                     // j==0 group: acc == q_0
            s_inv[(t + 1) & 1] = rcp_approx(acc);
            s_q0[t] = acc;                  // logged in parallel at the end
            const int tg = s_tgt[t];        // gold from the raw tile (resident)
            goldAcc += tiles[(size_t)(t & (NBUF - 1)) * TILE_ELEMS
                             + (tg / NTAG) * RS + (tg % NTAG)];
        }

        // staging: one commit per step (tile t+4 or empty), constant wait 2
        if (t + 4 < len)
            load_tile(tbase0 + (uint32_t)(((t + 4) & (NBUF - 1)) * TILE_ELEMS * 4),
                      fb + (size_t)(t + 4) * (NTAG * NTAG), tid);
        cp_commit();
        cp_wait2();             // all but 2 newest groups done -> tile t+2 resident
        __syncthreads();        // publish P_t / s_inv; tile t+2 visible to all warps

        // off-chain prefetch for iter t+1 (P_t, inv) and iter t+2 (exp of tile t+2)
        #pragma unroll
        for (int k = 0; k < 6; ++k) Pr[k] = P[(t & 1) * NTAG + s * 6 + k];
        inv = s_inv[(t + 1) & 1];
        if (t + 2 < len) {
            const float* En = tiles + (size_t)((t + 2) & (NBUF - 1)) * TILE_ELEMS + co;
            #pragma unroll
            for (int k = 0; k < 6; ++k) w[t & 1][k] = __expf(En[k * RS]);
        }
    }

    // ---- epilogue: parallel logs + gold, fixed-order reduction ----
    float lg = 0.0f;
    if (tid < len - 1) lg = __logf(s_q0[tid]);
    s_red[tid] = lg - goldAcc;
    __syncthreads();
    if (tid < 128) s_red[tid] += s_red[tid + 128] + s_red[tid + 256];
    __syncthreads();
    #pragma unroll
    for (int st = 64; st > 0; st >>= 1) {
        if (tid < st) s_red[tid] += s_red[tid + st];
        __syncthreads();
    }

    if (tid == 0) {
        const float val = s_red[0] + __logf(P[((len - 1) & 1) * NTAG + STOP_TAG]);
        g_partials[b] = val;
        __threadfence();
        const unsigned done = atomicAdd(&g_count, 1);
        s_isLast[0] = (done == BB - 1) ? 1 : 0;
    }
    __syncthreads();

    // Last CTA reduces the 128 partials (fixed tree -> deterministic).
    if (s_isLast[0]) {
        if (tid < BB) s_red[tid] = g_partials[tid];
        __syncthreads();
        #pragma unroll
        for (int st = BB / 2; st > 0; st >>= 1) {
            if (tid < st) s_red[tid] += s_red[tid + st];
            __syncthreads();
        }
        if (tid == 0) {
            out[0] = s_red[0];
            g_count = 0;                    // reset for next graph replay
        }
    }
}

extern "C" void kernel_launch(void* const* d_in, const int* in_sizes, int n_in,
                              void* d_out, int out_size) {
    const float* feats   = nullptr;
    const void*  targets = nullptr;
    const void*  lengths = nullptr;
    for (int i = 0; i < n_in; ++i) {
        if (in_sizes[i] == BB * TT * NTAG * NTAG) feats   = (const float*)d_in[i];
        else if (in_sizes[i] == BB * TT)          targets = d_in[i];
        else if (in_sizes[i] == BB)               lengths = d_in[i];
    }
    cudaFuncSetAttribute(viterbi_fwd,
                         cudaFuncAttributeMaxDynamicSharedMemorySize, SMEM_BYTES);
    viterbi_fwd<<<BB, NTHREADS, SMEM_BYTES>>>(feats, targets, lengths, (float*)d_out);
}

// round 12
// speedup vs baseline: 1.0607x; 1.0607x over previous
#include <cuda_runtime.h>
#include <cstdint>

#define NTAG      48
#define START_TAG 46
#define STOP_TAG  47
#define BB        128
#define TT        256
#define RS        50                 // padded row stride: matvec LDS covers all 32 banks
#define TILE_ELEMS (NTAG * RS)       // 2400
#define NBUF      8                  // raw-tile ring; 6-step load->use distance
#define NTHREADS  384                // 12 warps; j = tid>>3, s = tid&7

// dynamic smem: tiles | P[2][48] | s_inv[2] | s_q0[256] | s_tgt[256] | s_red[384] | isLast
#define SMEM_FLOATS (NBUF * TILE_ELEMS + 96 + 2 + TT + TT + NTHREADS + 4)
#define SMEM_BYTES  (SMEM_FLOATS * 4)

__device__ float        g_partials[BB];
__device__ unsigned int g_count = 0;

__device__ __forceinline__ float rcp_approx(float x) {
    float y;
    asm("rcp.approx.f32 %0, %1;" : "=f"(y) : "f"(x));
    return y;
}
__device__ __forceinline__ void cp_async8(uint32_t dst, const void* src) {
    unsigned long long gsrc;
    asm volatile("cvta.to.global.u64 %0, %1;\n" : "=l"(gsrc) : "l"(src));
    asm volatile("cp.async.ca.shared.global [%0], [%1], 8;\n" :: "r"(dst), "l"(gsrc));
}
__device__ __forceinline__ void cp_commit() {
    asm volatile("cp.async.commit_group;\n" ::: "memory");
}
__device__ __forceinline__ void cp_wait5() {
    asm volatile("cp.async.wait_group 5;\n" ::: "memory");
}

// 48x48 f32 tile (192B rows) -> padded SMEM (200B stride). 3 x 8B per thread.
__device__ __forceinline__ void load_tile(uint32_t sbase, const float* g, int tid) {
    const int r0   = tid / 24;
    const int off8 = (tid % 24) * 8;
    #pragma unroll
    for (int it = 0; it < 3; ++it) {
        const int row = r0 + 16 * it;
        cp_async8(sbase + (uint32_t)(row * (RS * 4) + off8),
                  (const char*)g + row * (NTAG * 4) + off8);
    }
}

__global__ void __launch_bounds__(NTHREADS, 1) viterbi_fwd(
    const float* __restrict__ feats,
    const void* __restrict__ targets_raw,
    const void* __restrict__ lengths_raw,
    float* __restrict__ out)
{
    extern __shared__ __align__(16) float smem[];
    float* tiles    = smem;                       // NBUF * TILE_ELEMS (raw features)
    float* P        = smem + NBUF * TILE_ELEMS;   // 2 * 48
    float* s_inv    = P + 96;                     // 2
    float* s_q0     = s_inv + 2;                  // 256
    int*   s_tgt    = (int*)(s_q0 + TT);          // 256
    float* s_red    = (float*)(s_tgt + TT);       // 384
    int*   s_isLast = (int*)(s_red + NTHREADS);

    const int b   = blockIdx.x;
    const int tid = threadIdx.x;

    // dtype probe: genuine int64 length[0] lies in [1,256]; int32-misread >= 2^32.
    const long long probe = ((const long long*)lengths_raw)[0];
    const bool is64 = (probe >= 1 && probe <= TT);

    int len = is64 ? (int)((const long long*)lengths_raw)[b]
                   : ((const int*)lengths_raw)[b];
    if (len < 1)  len = 1;
    if (len > TT) len = TT;
    const float* fb = feats + (size_t)b * TT * (NTAG * NTAG);

    const uint32_t tbase0 = (uint32_t)__cvta_generic_to_shared(tiles);

    for (int c = tid; c < TT; c += NTHREADS) {
        int v = is64 ? (int)((const long long*)targets_raw)[(size_t)b * TT + c]
                     : ((const int*)targets_raw)[(size_t)b * TT + c];
        if (v < 0) v = 0;
        if (v >= NTAG * NTAG) v = NTAG * NTAG - 1;
        s_tgt[c] = v;
    }

    // ---- prologue: commit tiles 0..6 (one group each; empty if past end) ----
    #pragma unroll
    for (int p = 0; p < 7; ++p) {
        if (p < len)
            load_tile(tbase0 + (uint32_t)(p * TILE_ELEMS * 4),
                      fb + (size_t)p * (NTAG * NTAG), tid);
        cp_commit();
    }
    cp_wait5();                 // all but 5 newest groups done -> tiles 0,1 resident
    __syncthreads();            // visibility of tiles 0,1 + s_tgt

    // init: P_0[j] = exp(raw tile0[START,:]); gold t=0; scale for t=1.
    if (tid < NTAG) {
        const float p = __expf(tiles[START_TAG * RS + tid]);
        P[tid] = p;
        if (tid == 0) {
            s_inv[1] = rcp_approx(p);
            s_q0[0]  = p;
        }
    }
    float goldAcc = 0.0f;
    if (tid == 0) {
        const int tg = s_tgt[0];
        goldAcc = tiles[(tg / NTAG) * RS + (tg % NTAG)];
    }
    // no barrier here: step t=1 begins with commit/wait/bar below

    const int j = tid >> 3;                 // destination tag
    const int s = tid & 7;                  // source slice (6 rows)
    const int co = (s * 6) * RS + j;        // matvec base offset into a tile

    #pragma unroll 2
    for (int t = 1; t < len; ++t) {
        // one commit per step: tile t+6 (or empty), then constant wait 5.
        // Pending after commit: tiles t+2..t+6 -> tile t+1 resident (t even safer).
        if (t + 6 < len)
            load_tile(tbase0 + (uint32_t)(((t + 6) & (NBUF - 1)) * TILE_ELEMS * 4),
                      fb + (size_t)(t + 6) * (NTAG * NTAG), tid);
        cp_commit();
        cp_wait5();
        __syncthreads();        // cp.async visibility + P/s_inv publication

        const float* E   = tiles + (size_t)(t & (NBUF - 1)) * TILE_ELEMS + co;
        const float* Pc  = P + ((t + 1) & 1) * NTAG + s * 6;
        const float  inv = s_inv[t & 1];

        // raw loads -> exp inline -> FMA tree
        const float w0 = __expf(E[0 * RS]);
        const float w1 = __expf(E[1 * RS]);
        const float w2 = __expf(E[2 * RS]);
        const float w3 = __expf(E[3 * RS]);
        const float w4 = __expf(E[4 * RS]);
        const float w5 = __expf(E[5 * RS]);

        float acc0 = w0 * Pc[0] + w1 * Pc[1] + w2 * Pc[2];
        float acc1 = w3 * Pc[3] + w4 * Pc[4] + w5 * Pc[5];
        float acc  = (acc0 + acc1) * inv;
        acc += __shfl_xor_sync(0xffffffffu, acc, 1);
        acc += __shfl_xor_sync(0xffffffffu, acc, 2);
        acc += __shfl_xor_sync(0xffffffffu, acc, 4);

        if (s == 0) P[(t & 1) * NTAG + j] = acc;
        if (tid == 0) {                     // j==0 group: acc == q_0
            s_inv[(t + 1) & 1] = rcp_approx(acc);
            s_q0[t] = acc;                  // logged in parallel at the end
            const int tg = s_tgt[t];        // gold from the raw tile (resident)
            goldAcc += tiles[(size_t)(t & (NBUF - 1)) * TILE_ELEMS
                             + (tg / NTAG) * RS + (tg % NTAG)];
        }
    }
    __syncthreads();            // last P / s_q0 published

    // ---- epilogue: parallel logs + gold, fixed-order reduction ----
    float lg = 0.0f;
    if (tid < len - 1) lg = __logf(s_q0[tid]);
    s_red[tid] = lg - goldAcc;
    __syncthreads();
    if (tid < 128) s_red[tid] += s_red[tid + 128] + s_red[tid + 256];
    __syncthreads();
    #pragma unroll
    for (int st = 64; st > 0; st >>= 1) {
        if (tid < st) s_red[tid] += s_red[tid + st];
        __syncthreads();
    }

    if (tid == 0) {
        const float val = s_red[0] + __logf(P[((len - 1) & 1) * NTAG + STOP_TAG]);
        g_partials[b] = val;
        __threadfence();
        const unsigned done = atomicAdd(&g_count, 1);
        s_isLast[0] = (done == BB - 1) ? 1 : 0;
    }
    __syncthreads();

    // Last CTA reduces the 128 partials (fixed tree -> deterministic).
    if (s_isLast[0]) {
        if (tid < BB) s_red[tid] = g_partials[tid];
        __syncthreads();
        #pragma unroll
        for (int st = BB / 2; st > 0; st >>= 1) {
            if (tid < st) s_red[tid] += s_red[tid + st];
            __syncthreads();
        }
        if (tid == 0) {
            out[0] = s_red[0];
            g_count = 0;                    // reset for next graph replay
        }
    }
}

extern "C" void kernel_launch(void* const* d_in, const int* in_sizes, int n_in,
                              void* d_out, int out_size) {
    const float* feats   = nullptr;
    const void*  targets = nullptr;
    const void*  lengths = nullptr;
    for (int i = 0; i < n_in; ++i) {
        if (in_sizes[i] == BB * TT * NTAG * NTAG) feats   = (const float*)d_in[i];
        else if (in_sizes[i] == BB * TT)          targets = d_in[i];
        else if (in_sizes[i] == BB)               lengths = d_in[i];
    }
    cudaFuncSetAttribute(viterbi_fwd,
                         cudaFuncAttributeMaxDynamicSharedMemorySize, SMEM_BYTES);
    viterbi_fwd<<<BB, NTHREADS, SMEM_BYTES>>>(feats, targets, lengths, (float*)d_out);
}